// round 5
// baseline (speedup 1.0000x reference)
#include <cuda_runtime.h>
#include <cuda_bf16.h>
#include <math.h>

#define NR   8192     // rows of z
#define HD   256      // feature dim
#define NC   64       // clusters
#define RPB  64       // rows per block
#define TPB  1024     // 32 warps: 4 warp_m x 8 warp_n, warp tile m16n8
#define NBLK (NR / RPB)   // 128 blocks, one wave, 1 block/SM

// dynamic smem tiles, each [64][256] bf16 = 32KB, row stride 512B, XOR-swizzled
#define OFF_ZH 0
#define OFF_ZL 32768
#define OFF_CH 65536
#define OFF_CL 98304
#define SMEM_B 131072

__device__ float g_partT[NC * NBLK];  // transposed partial colsums [col][block]
__device__ unsigned int g_arrive;     // epoch ticket counter (static zero-init)

#define LDSM4(r, addr) \
    asm volatile("ldmatrix.sync.aligned.m8n8.x4.shared.b16 {%0,%1,%2,%3}, [%4];" \
        : "=r"((r)[0]), "=r"((r)[1]), "=r"((r)[2]), "=r"((r)[3]) : "r"(addr))

#define LDSM2(r, addr) \
    asm volatile("ldmatrix.sync.aligned.m8n8.x2.shared.b16 {%0,%1}, [%2];" \
        : "=r"((r)[0]), "=r"((r)[1]) : "r"(addr))

#define MMA16816(d, a, b0, b1) \
    asm volatile("mma.sync.aligned.m16n8k16.row.col.f32.bf16.bf16.f32 " \
        "{%0,%1,%2,%3},{%4,%5,%6,%7},{%8,%9},{%0,%1,%2,%3};" \
        : "+f"((d)[0]), "+f"((d)[1]), "+f"((d)[2]), "+f"((d)[3]) \
        : "r"((a)[0]), "r"((a)[1]), "r"((a)[2]), "r"((a)[3]), "r"(b0), "r"(b1))

__device__ __forceinline__ unsigned bf2_bits(__nv_bfloat162 h) {
    return *reinterpret_cast<unsigned*>(&h);
}

// Convert 64 fp32 rows into hi/lo bf16 swizzled smem + row norms.
// 1024 threads: 16 lanes per row, 4 float4 per lane.
__device__ __forceinline__ void convert_rows64(const float4* __restrict__ g4,
                                               char* hi, char* lo,
                                               float* norm_out, int t) {
    const int row = t >> 4;
    const int l16 = t & 15;
    float acc = 0.f;
    #pragma unroll
    for (int j = 0; j < 4; j++) {
        const int c4 = l16 + 16 * j;               // float4 index, k0 = 4*c4
        float4 v = g4[row * (HD / 4) + c4];
        acc = fmaf(v.x, v.x, acc);
        acc = fmaf(v.y, v.y, acc);
        acc = fmaf(v.z, v.z, acc);
        acc = fmaf(v.w, v.w, acc);

        __nv_bfloat162 h01 = __floats2bfloat162_rn(v.x, v.y);
        __nv_bfloat162 h23 = __floats2bfloat162_rn(v.z, v.w);
        float lx = v.x - __low2float(h01);
        float ly = v.y - __high2float(h01);
        float lz = v.z - __low2float(h23);
        float lw = v.w - __high2float(h23);
        __nv_bfloat162 l01 = __floats2bfloat162_rn(lx, ly);
        __nv_bfloat162 l23 = __floats2bfloat162_rn(lz, lw);

        const int byteoff = 8 * c4;
        const int chunk = byteoff >> 4;
        const int inner = byteoff & 15;            // 0 or 8
        const unsigned off = row * 512 + (((chunk ^ (row & 7)) << 4) | inner);
        *(uint2*)(hi + off) = make_uint2(bf2_bits(h01), bf2_bits(h23));
        *(uint2*)(lo + off) = make_uint2(bf2_bits(l01), bf2_bits(l23));
    }
    acc += __shfl_xor_sync(0xffffffffu, acc, 1);
    acc += __shfl_xor_sync(0xffffffffu, acc, 2);
    acc += __shfl_xor_sync(0xffffffffu, acc, 4);
    acc += __shfl_xor_sync(0xffffffffu, acc, 8);
    if (l16 == 0) norm_out[row] = acc;
}

__global__ void __launch_bounds__(TPB, 1)
fused_kernel(const float* __restrict__ z, const float* __restrict__ cent,
             float* __restrict__ Q, float* __restrict__ P) {
    extern __shared__ char smem[];
    char* zh = smem + OFF_ZH;
    char* zl = smem + OFF_ZL;
    char* ch = smem + OFF_CH;
    char* cl = smem + OFF_CL;
    __shared__ float s_zn[RPB], s_cn[NC];
    __shared__ float s_rs[RPB], s_cs[NC], s_ct[NC], s_pr[RPB];

    const int t = threadIdx.x;
    const unsigned sb = (unsigned)__cvta_generic_to_shared(smem);

    if (t < NC) { s_cs[t] = 0.f; s_ct[t] = 0.f; }
    if (t < RPB) { s_rs[t] = 0.f; s_pr[t] = 0.f; }

    // ---- Phase 1: load + split-convert z tile and centroid matrix ----
    convert_rows64((const float4*)(z + (size_t)blockIdx.x * RPB * HD), zh, zl, s_zn, t);
    convert_rows64((const float4*)cent, ch, cl, s_cn, t);
    __syncthreads();

    // ---- Phase 2: GEMM mainloop (3-term split bf16 mma, m16n8 per warp) ----
    const int lane = t & 31, wid = t >> 5;
    const int wm = wid >> 3;          // 0..3 -> rows wm*16
    const int wn = wid & 7;           // 0..7 -> cols wn*8

    const int tile = lane >> 3, rit = lane & 7;
    const int arow = wm * 16 + rit + 8 * (tile & 1);
    const int acb = tile >> 1;
    const unsigned azh = sb + OFF_ZH + arow * 512;
    const unsigned azl = sb + OFF_ZL + arow * 512;
    const int axor = arow & 7;

    const int brow = wn * 8 + rit;            // lanes 0..15 meaningful
    const int bkb = tile & 1;                  // k-half select for x2
    const unsigned bch = sb + OFF_CH + brow * 512;
    const unsigned bcl = sb + OFF_CL + brow * 512;
    const int bxor = brow & 7;

    float d[4] = {0.f, 0.f, 0.f, 0.f};

    #pragma unroll
    for (int ks = 0; ks < 16; ks++) {
        const unsigned aoff = (unsigned)(((2 * ks + acb) ^ axor) << 4);
        const unsigned boff = (unsigned)(((2 * ks + bkb) ^ bxor) << 4);
        unsigned ah[4], al[4], bh[2], bl[2];
        LDSM4(ah, azh + aoff);
        LDSM2(bh, bch + boff);
        LDSM4(al, azl + aoff);
        LDSM2(bl, bcl + boff);
        MMA16816(d, ah, bh[0], bh[1]);
        MMA16816(d, ah, bl[0], bl[1]);
        MMA16816(d, al, bh[0], bh[1]);
    }

    // ---- Phase 3: epilogue -> Q ----
    const int gid = lane >> 2, tig = lane & 3;
    const int R0 = wm * 16 + gid, R1 = R0 + 8;
    const int c0 = wn * 8 + 2 * tig, c1 = c0 + 1;
    const float znA = s_zn[R0], znB = s_zn[R1];
    const float cn0 = s_cn[c0], cn1 = s_cn[c1];

    float q00 = 1.f / (1.f + sqrtf(fmaxf(fmaf(-2.f, d[0], znA + cn0), 0.f)));
    float q01 = 1.f / (1.f + sqrtf(fmaxf(fmaf(-2.f, d[1], znA + cn1), 0.f)));
    float q02 = 1.f / (1.f + sqrtf(fmaxf(fmaf(-2.f, d[2], znB + cn0), 0.f)));
    float q03 = 1.f / (1.f + sqrtf(fmaxf(fmaf(-2.f, d[3], znB + cn1), 0.f)));

    // row sums: reduce over tig lanes, then cross-warp smem atomics (8 wn warps)
    float rs0 = q00 + q01;
    float rs1 = q02 + q03;
    rs0 += __shfl_xor_sync(0xffffffffu, rs0, 1);
    rs0 += __shfl_xor_sync(0xffffffffu, rs0, 2);
    rs1 += __shfl_xor_sync(0xffffffffu, rs1, 1);
    rs1 += __shfl_xor_sync(0xffffffffu, rs1, 2);
    if (tig == 0) { atomicAdd(&s_rs[R0], rs0); atomicAdd(&s_rs[R1], rs1); }
    __syncthreads();

    const float ir0 = 1.f / s_rs[R0], ir1 = 1.f / s_rs[R1];
    q00 *= ir0; q01 *= ir0;
    q02 *= ir1; q03 *= ir1;

    const int gA = blockIdx.x * RPB + R0;
    const int gB = blockIdx.x * RPB + R1;
    *(float2*)(Q + (size_t)gA * NC + c0) = make_float2(q00, q01);
    *(float2*)(Q + (size_t)gB * NC + c0) = make_float2(q02, q03);

    // column sums of normalized Q: reduce over gid lanes, atomics from lanes 0-3
    float cs0 = q00 + q02, cs1 = q01 + q03;
    #pragma unroll
    for (int m = 4; m <= 16; m <<= 1) {
        cs0 += __shfl_xor_sync(0xffffffffu, cs0, m);
        cs1 += __shfl_xor_sync(0xffffffffu, cs1, m);
    }
    if (lane < 4) { atomicAdd(&s_cs[c0], cs0); atomicAdd(&s_cs[c1], cs1); }
    __syncthreads();

    // publish block partial colsums (transposed: [col][block])
    if (t < NC) g_partT[t * NBLK + blockIdx.x] = s_cs[t];
    __threadfence();
    __syncthreads();

    // ---- single-wave grid sync (epoch ticket; replay-deterministic) ----
    if (t == 0) {
        unsigned ticket;
        asm volatile("atom.global.add.release.gpu.u32 %0, [%1], 1;"
                     : "=r"(ticket) : "l"(&g_arrive) : "memory");
        const unsigned target = (ticket / NBLK + 1u) * NBLK;
        unsigned v;
        do {
            asm volatile("ld.global.acquire.gpu.u32 %0, [%1];"
                         : "=r"(v) : "l"(&g_arrive) : "memory");
        } while (v < target);
    }
    __syncthreads();
    __threadfence();

    // total column sums: 16 segments x 8 contiguous floats per column
    {
        const int col = t >> 4, seg = t & 15;
        const float4* p4 = (const float4*)(g_partT + col * NBLK + seg * 8);
        float4 u = __ldcg(p4);
        float4 w = __ldcg(p4 + 1);
        float s = ((u.x + u.y) + (u.z + u.w)) + ((w.x + w.y) + (w.z + w.w));
        s += __shfl_xor_sync(0xffffffffu, s, 1);
        s += __shfl_xor_sync(0xffffffffu, s, 2);
        s += __shfl_xor_sync(0xffffffffu, s, 4);
        s += __shfl_xor_sync(0xffffffffu, s, 8);
        if (seg == 0) s_ct[col] = s;
    }
    __syncthreads();

    // ---- Phase 4: P from in-register Q ----
    const float ic0 = 1.f / s_ct[c0], ic1 = 1.f / s_ct[c1];

    float p00 = q00 * q00 * ic0, p01 = q01 * q01 * ic1;
    float p02 = q02 * q02 * ic0, p03 = q03 * q03 * ic1;

    float ps0 = p00 + p01;
    float ps1 = p02 + p03;
    ps0 += __shfl_xor_sync(0xffffffffu, ps0, 1);
    ps0 += __shfl_xor_sync(0xffffffffu, ps0, 2);
    ps1 += __shfl_xor_sync(0xffffffffu, ps1, 1);
    ps1 += __shfl_xor_sync(0xffffffffu, ps1, 2);
    if (tig == 0) { atomicAdd(&s_pr[R0], ps0); atomicAdd(&s_pr[R1], ps1); }
    __syncthreads();

    const float ip0 = 1.f / s_pr[R0], ip1 = 1.f / s_pr[R1];
    *(float2*)(P + (size_t)gA * NC + c0) = make_float2(p00 * ip0, p01 * ip0);
    *(float2*)(P + (size_t)gB * NC + c0) = make_float2(p02 * ip1, p03 * ip1);
}

extern "C" void kernel_launch(void* const* d_in, const int* in_sizes, int n_in,
                              void* d_out, int out_size) {
    const float* z    = (const float*)d_in[0];   // (8192, 256) f32
    const float* cent = (const float*)d_in[1];   // (64, 256)   f32
    float* Q = (float*)d_out;
    float* P = Q + (size_t)NR * NC;

    cudaFuncSetAttribute(fused_kernel, cudaFuncAttributeMaxDynamicSharedMemorySize, SMEM_B);
    fused_kernel<<<NBLK, TPB, SMEM_B>>>(z, cent, Q, P);
}

// round 6
// speedup vs baseline: 1.1210x; 1.1210x over previous
#include <cuda_runtime.h>
#include <cuda_bf16.h>
#include <math.h>

#define NR   8192     // rows of z
#define HD   256      // feature dim
#define NC   64       // clusters
#define RPB  64       // rows per block
#define TPB  512      // 16 warps: 4 warp_m x 4 warp_n, warp tile m16n16
#define NBLK (NR / RPB)   // 128 blocks, one wave, 1 block/SM

// smem tiles, each [64][256] bf16 = 32KB, row stride 512B, XOR-swizzled
#define OFF_ZH 0
#define OFF_CH 32768
#define OFF_CL 65536
#define SMEM_B 98304

__device__ float g_partT[NC * NBLK];  // transposed partial colsums [col][block]
__device__ unsigned int g_arrive;     // epoch ticket counter (static zero-init)

#define LDSM4(r, addr) \
    asm volatile("ldmatrix.sync.aligned.m8n8.x4.shared.b16 {%0,%1,%2,%3}, [%4];" \
        : "=r"((r)[0]), "=r"((r)[1]), "=r"((r)[2]), "=r"((r)[3]) : "r"(addr))

#define MMA16816(d, a, b0, b1) \
    asm volatile("mma.sync.aligned.m16n8k16.row.col.f32.bf16.bf16.f32 " \
        "{%0,%1,%2,%3},{%4,%5,%6,%7},{%8,%9},{%0,%1,%2,%3};" \
        : "+f"((d)[0]), "+f"((d)[1]), "+f"((d)[2]), "+f"((d)[3]) \
        : "r"((a)[0]), "r"((a)[1]), "r"((a)[2]), "r"((a)[3]), "r"(b0), "r"(b1))

__device__ __forceinline__ unsigned bf2_bits(__nv_bfloat162 h) {
    return *reinterpret_cast<unsigned*>(&h);
}

// hi-only convert (for z): 8 lanes/row, 8 float4/lane; fp32 row norms.
__device__ __forceinline__ void convert_hi(const float4* __restrict__ g4,
                                           char* hi, float* norm_out, int t) {
    const int row = t >> 3;
    const int l8 = t & 7;
    float acc = 0.f;
    #pragma unroll
    for (int j = 0; j < 8; j++) {
        const int c4 = l8 + 8 * j;
        float4 v = g4[row * (HD / 4) + c4];
        acc = fmaf(v.x, v.x, acc);
        acc = fmaf(v.y, v.y, acc);
        acc = fmaf(v.z, v.z, acc);
        acc = fmaf(v.w, v.w, acc);

        __nv_bfloat162 h01 = __floats2bfloat162_rn(v.x, v.y);
        __nv_bfloat162 h23 = __floats2bfloat162_rn(v.z, v.w);

        const int byteoff = 8 * c4;
        const int chunk = byteoff >> 4;
        const int inner = byteoff & 15;
        const unsigned off = row * 512 + (((chunk ^ (row & 7)) << 4) | inner);
        *(uint2*)(hi + off) = make_uint2(bf2_bits(h01), bf2_bits(h23));
    }
    acc += __shfl_xor_sync(0xffffffffu, acc, 1);
    acc += __shfl_xor_sync(0xffffffffu, acc, 2);
    acc += __shfl_xor_sync(0xffffffffu, acc, 4);
    if (l8 == 0) norm_out[row] = acc;
}

// hi/lo split convert (for centroids).
__device__ __forceinline__ void convert_hilo(const float4* __restrict__ g4,
                                             char* hi, char* lo,
                                             float* norm_out, int t) {
    const int row = t >> 3;
    const int l8 = t & 7;
    float acc = 0.f;
    #pragma unroll
    for (int j = 0; j < 8; j++) {
        const int c4 = l8 + 8 * j;
        float4 v = g4[row * (HD / 4) + c4];
        acc = fmaf(v.x, v.x, acc);
        acc = fmaf(v.y, v.y, acc);
        acc = fmaf(v.z, v.z, acc);
        acc = fmaf(v.w, v.w, acc);

        __nv_bfloat162 h01 = __floats2bfloat162_rn(v.x, v.y);
        __nv_bfloat162 h23 = __floats2bfloat162_rn(v.z, v.w);
        float lx = v.x - __low2float(h01);
        float ly = v.y - __high2float(h01);
        float lz = v.z - __low2float(h23);
        float lw = v.w - __high2float(h23);
        __nv_bfloat162 l01 = __floats2bfloat162_rn(lx, ly);
        __nv_bfloat162 l23 = __floats2bfloat162_rn(lz, lw);

        const int byteoff = 8 * c4;
        const int chunk = byteoff >> 4;
        const int inner = byteoff & 15;
        const unsigned off = row * 512 + (((chunk ^ (row & 7)) << 4) | inner);
        *(uint2*)(hi + off) = make_uint2(bf2_bits(h01), bf2_bits(h23));
        *(uint2*)(lo + off) = make_uint2(bf2_bits(l01), bf2_bits(l23));
    }
    acc += __shfl_xor_sync(0xffffffffu, acc, 1);
    acc += __shfl_xor_sync(0xffffffffu, acc, 2);
    acc += __shfl_xor_sync(0xffffffffu, acc, 4);
    if (l8 == 0) norm_out[row] = acc;
}

__global__ void __launch_bounds__(TPB, 1)
fused_kernel(const float* __restrict__ z, const float* __restrict__ cent,
             float* __restrict__ Q, float* __restrict__ P) {
    extern __shared__ char smem[];
    char* zh = smem + OFF_ZH;
    char* ch = smem + OFF_CH;
    char* cl = smem + OFF_CL;
    __shared__ float s_zn[RPB], s_cn[NC];
    __shared__ float s_rs[RPB], s_cs[NC], s_ct[NC], s_pr[RPB];

    const int t = threadIdx.x;
    const unsigned sb = (unsigned)__cvta_generic_to_shared(smem);

    if (t < NC) { s_cs[t] = 0.f; s_ct[t] = 0.f; }
    if (t < RPB) { s_rs[t] = 0.f; s_pr[t] = 0.f; }

    // ---- Phase 1: convert z (hi) and centroids (hi/lo) into smem ----
    convert_hi((const float4*)(z + (size_t)blockIdx.x * RPB * HD), zh, s_zn, t);
    convert_hilo((const float4*)cent, ch, cl, s_cn, t);
    __syncthreads();

    // ---- Phase 2: GEMM mainloop (2-term: zh*ch + zh*cl) ----
    const int lane = t & 31, wid = t >> 5;
    const int wm = wid >> 2, wn = wid & 3;
    const int tile = lane >> 3, rit = lane & 7;

    const int arow = wm * 16 + rit + 8 * (tile & 1);
    const int acb = tile >> 1;
    const unsigned azh = sb + OFF_ZH + arow * 512;
    const int axor = arow & 7;

    const int brow = wn * 16 + rit + 8 * (tile >> 1);
    const int bcb = tile & 1;
    const unsigned bch = sb + OFF_CH + brow * 512;
    const unsigned bcl = sb + OFF_CL + brow * 512;
    const int bxor = brow & 7;

    float d0[4] = {0.f, 0.f, 0.f, 0.f};   // n-half 0
    float d1[4] = {0.f, 0.f, 0.f, 0.f};   // n-half 1

    #pragma unroll
    for (int ks = 0; ks < 16; ks++) {
        const unsigned aoff = (unsigned)(((2 * ks + acb) ^ axor) << 4);
        const unsigned boff = (unsigned)(((2 * ks + bcb) ^ bxor) << 4);
        unsigned ah[4], bhf[4], blf[4];
        LDSM4(ah, azh + aoff);
        LDSM4(bhf, bch + boff);
        LDSM4(blf, bcl + boff);
        MMA16816(d0, ah, bhf[0], bhf[1]);
        MMA16816(d1, ah, bhf[2], bhf[3]);
        MMA16816(d0, ah, blf[0], blf[1]);
        MMA16816(d1, ah, blf[2], blf[3]);
    }

    // ---- Phase 3: epilogue -> Q ----
    const int gid = lane >> 2, tig = lane & 3;
    const int R0 = wm * 16 + gid, R1 = R0 + 8;
    const float znA = s_zn[R0], znB = s_zn[R1];
    const int c00 = wn * 16 + 2 * tig;
    const int c10 = c00 + 8;
    const float cnA0 = s_cn[c00], cnA1 = s_cn[c00 + 1];
    const float cnB0 = s_cn[c10], cnB1 = s_cn[c10 + 1];

    float q00 = 1.f / (1.f + sqrtf(fmaxf(fmaf(-2.f, d0[0], znA + cnA0), 0.f)));
    float q01 = 1.f / (1.f + sqrtf(fmaxf(fmaf(-2.f, d0[1], znA + cnA1), 0.f)));
    float q02 = 1.f / (1.f + sqrtf(fmaxf(fmaf(-2.f, d0[2], znB + cnA0), 0.f)));
    float q03 = 1.f / (1.f + sqrtf(fmaxf(fmaf(-2.f, d0[3], znB + cnA1), 0.f)));
    float q10 = 1.f / (1.f + sqrtf(fmaxf(fmaf(-2.f, d1[0], znA + cnB0), 0.f)));
    float q11 = 1.f / (1.f + sqrtf(fmaxf(fmaf(-2.f, d1[1], znA + cnB1), 0.f)));
    float q12 = 1.f / (1.f + sqrtf(fmaxf(fmaf(-2.f, d1[2], znB + cnB0), 0.f)));
    float q13 = 1.f / (1.f + sqrtf(fmaxf(fmaf(-2.f, d1[3], znB + cnB1), 0.f)));

    float rs0 = (q00 + q01) + (q10 + q11);
    float rs1 = (q02 + q03) + (q12 + q13);
    rs0 += __shfl_xor_sync(0xffffffffu, rs0, 1);
    rs0 += __shfl_xor_sync(0xffffffffu, rs0, 2);
    rs1 += __shfl_xor_sync(0xffffffffu, rs1, 1);
    rs1 += __shfl_xor_sync(0xffffffffu, rs1, 2);
    if (tig == 0) { atomicAdd(&s_rs[R0], rs0); atomicAdd(&s_rs[R1], rs1); }
    __syncthreads();

    const float ir0 = 1.f / s_rs[R0], ir1 = 1.f / s_rs[R1];
    q00 *= ir0; q01 *= ir0; q10 *= ir0; q11 *= ir0;
    q02 *= ir1; q03 *= ir1; q12 *= ir1; q13 *= ir1;

    const int gA = blockIdx.x * RPB + R0;
    const int gB = blockIdx.x * RPB + R1;
    *(float2*)(Q + (size_t)gA * NC + c00) = make_float2(q00, q01);
    *(float2*)(Q + (size_t)gB * NC + c00) = make_float2(q02, q03);
    *(float2*)(Q + (size_t)gA * NC + c10) = make_float2(q10, q11);
    *(float2*)(Q + (size_t)gB * NC + c10) = make_float2(q12, q13);

    float cA0 = q00 + q02, cA1 = q01 + q03;
    float cB0 = q10 + q12, cB1 = q11 + q13;
    #pragma unroll
    for (int m = 4; m <= 16; m <<= 1) {
        cA0 += __shfl_xor_sync(0xffffffffu, cA0, m);
        cA1 += __shfl_xor_sync(0xffffffffu, cA1, m);
        cB0 += __shfl_xor_sync(0xffffffffu, cB0, m);
        cB1 += __shfl_xor_sync(0xffffffffu, cB1, m);
    }
    if (lane < 4) {
        atomicAdd(&s_cs[c00], cA0);
        atomicAdd(&s_cs[c00 + 1], cA1);
        atomicAdd(&s_cs[c10], cB0);
        atomicAdd(&s_cs[c10 + 1], cB1);
    }
    __syncthreads();

    // publish block partial colsums (transposed: [col][block])
    if (t < NC) g_partT[t * NBLK + blockIdx.x] = s_cs[t];
    __threadfence();
    __syncthreads();

    // ---- single-wave grid sync (epoch ticket; replay-deterministic) ----
    if (t == 0) {
        unsigned ticket;
        asm volatile("atom.global.add.release.gpu.u32 %0, [%1], 1;"
                     : "=r"(ticket) : "l"(&g_arrive) : "memory");
        const unsigned target = (ticket / NBLK + 1u) * NBLK;
        unsigned v;
        do {
            asm volatile("ld.global.acquire.gpu.u32 %0, [%1];"
                         : "=r"(v) : "l"(&g_arrive) : "memory");
        } while (v < target);
    }
    __syncthreads();
    __threadfence();

    // total column sums: 8 segments x 16 contiguous floats per column
    {
        const int col = t >> 3, seg = t & 7;
        const float4* p4 = (const float4*)(g_partT + col * NBLK + seg * 16);
        float4 u = __ldcg(p4);
        float4 w = __ldcg(p4 + 1);
        float4 x = __ldcg(p4 + 2);
        float4 y = __ldcg(p4 + 3);
        float s = (((u.x + u.y) + (u.z + u.w)) + ((w.x + w.y) + (w.z + w.w)))
                + (((x.x + x.y) + (x.z + x.w)) + ((y.x + y.y) + (y.z + y.w)));
        s += __shfl_xor_sync(0xffffffffu, s, 1);
        s += __shfl_xor_sync(0xffffffffu, s, 2);
        s += __shfl_xor_sync(0xffffffffu, s, 4);
        if (seg == 0) s_ct[col] = s;
    }
    __syncthreads();

    // ---- Phase 4: P from in-register Q ----
    const float icA0 = 1.f / s_ct[c00], icA1 = 1.f / s_ct[c00 + 1];
    const float icB0 = 1.f / s_ct[c10], icB1 = 1.f / s_ct[c10 + 1];

    float p00 = q00 * q00 * icA0, p01 = q01 * q01 * icA1;
    float p02 = q02 * q02 * icA0, p03 = q03 * q03 * icA1;
    float p10 = q10 * q10 * icB0, p11 = q11 * q11 * icB1;
    float p12 = q12 * q12 * icB0, p13 = q13 * q13 * icB1;

    float ps0 = (p00 + p01) + (p10 + p11);
    float ps1 = (p02 + p03) + (p12 + p13);
    ps0 += __shfl_xor_sync(0xffffffffu, ps0, 1);
    ps0 += __shfl_xor_sync(0xffffffffu, ps0, 2);
    ps1 += __shfl_xor_sync(0xffffffffu, ps1, 1);
    ps1 += __shfl_xor_sync(0xffffffffu, ps1, 2);
    if (tig == 0) { atomicAdd(&s_pr[R0], ps0); atomicAdd(&s_pr[R1], ps1); }
    __syncthreads();

    const float ip0 = 1.f / s_pr[R0], ip1 = 1.f / s_pr[R1];
    *(float2*)(P + (size_t)gA * NC + c00) = make_float2(p00 * ip0, p01 * ip0);
    *(float2*)(P + (size_t)gB * NC + c00) = make_float2(p02 * ip1, p03 * ip1);
    *(float2*)(P + (size_t)gA * NC + c10) = make_float2(p10 * ip0, p11 * ip0);
    *(float2*)(P + (size_t)gB * NC + c10) = make_float2(p12 * ip1, p13 * ip1);
}

extern "C" void kernel_launch(void* const* d_in, const int* in_sizes, int n_in,
                              void* d_out, int out_size) {
    const float* z    = (const float*)d_in[0];   // (8192, 256) f32
    const float* cent = (const float*)d_in[1];   // (64, 256)   f32
    float* Q = (float*)d_out;
    float* P = Q + (size_t)NR * NC;

    cudaFuncSetAttribute(fused_kernel, cudaFuncAttributeMaxDynamicSharedMemorySize, SMEM_B);
    fused_kernel<<<NBLK, TPB, SMEM_B>>>(z, cent, Q, P);
}